// round 4
// baseline (speedup 1.0000x reference)
#include <cuda_runtime.h>
#include <cstdint>

// ---------------- config ----------------
#define CTAS        1024
#define THREADS     512
#define WARPS       16
#define NCHUNK      2               // double-chunks (32 rows) per warp
#define ROWS_WARP   64              // 1024*16*64 = 1,048,576
#define UNIT_ROWS   16
#define UNIT_BYTES  4096
#define NSLOTS      3

// smem: FB (fragment-major W, 16 KB) then per-warp 3-slot rings
#define FB_BYTES    16384
#define SMEM_X      FB_BYTES
#define SMEM_TOTAL  (FB_BYTES + WARPS * NSLOTS * UNIT_BYTES)   // 212992

// ---------------- math constants ----------------
#define C_SCALE_L2E  4.3280851227f   // 3 * log2(e)
#define C_CLAMP_L2E 14.4269504089f   // 10 * log2(e)
#define C_LN2        0.6931471806f

// ---------------- helpers ----------------
static __device__ __forceinline__ uint32_t smem_u32(const void* p) {
    uint32_t a;
    asm("{ .reg .u64 t; cvta.to.shared.u64 t, %1; cvt.u32.u64 %0, t; }"
        : "=r"(a) : "l"(p));
    return a;
}
static __device__ __forceinline__ void cp16(uint32_t s, const void* g) {
    asm volatile("cp.async.cg.shared.global [%0], [%1], 16;" :: "r"(s), "l"(g));
}
#define CP_COMMIT() asm volatile("cp.async.commit_group;" ::: "memory")
#define CP_WAIT1()  asm volatile("cp.async.wait_group 1;" ::: "memory")

static __device__ __forceinline__ float exp2_fast(float x) {
    float r; asm("ex2.approx.ftz.f32 %0, %1;" : "=f"(r) : "f"(x)); return r;
}
static __device__ __forceinline__ float lg2_fast(float x) {
    float r; asm("lg2.approx.f32 %0, %1;" : "=f"(r) : "f"(x)); return r;
}
static __device__ __forceinline__ float rcp_fast(float x) {
    float r; asm("rcp.approx.ftz.f32 %0, %1;" : "=f"(r) : "f"(x)); return r;
}
static __device__ __forceinline__ uint32_t f2tf32(float v) {
    uint32_t r; asm("cvt.rna.tf32.f32 %0, %1;" : "=r"(r) : "f"(v)); return r;
}
static __device__ __forceinline__ uint32_t lds32(const char* smem, uint32_t off) {
    return *reinterpret_cast<const uint32_t*>(smem + off);
}

// mma.sync m16n8k8 tf32
static __device__ __forceinline__ void mma_tf32(
    float* d, const uint32_t* a, uint32_t b0, uint32_t b1) {
    asm volatile(
        "mma.sync.aligned.m16n8k8.row.col.f32.tf32.tf32.f32 "
        "{%0,%1,%2,%3}, {%4,%5,%6,%7}, {%8,%9}, {%0,%1,%2,%3};"
        : "+f"(d[0]), "+f"(d[1]), "+f"(d[2]), "+f"(d[3])
        : "r"(a[0]), "r"(a[1]), "r"(a[2]), "r"(a[3]), "r"(b0), "r"(b1));
}

static __device__ __forceinline__ float expv(float z) {
    float w = fminf(fmaxf(z * C_SCALE_L2E, -C_CLAMP_L2E), C_CLAMP_L2E);
    return exp2_fast(w);
}
// mish(ln s): e^(ln s) == s exactly -> tanh(softplus) = ((1+s)^2-1)/((1+s)^2+1)
static __device__ __forceinline__ float mish_of_ln(float s) {
    float lse = C_LN2 * lg2_fast(s);
    float up  = s + 1.0f;
    float q   = up * up;
    return lse * (q - 1.0f) * rcp_fast(q + 1.0f);
}

// load one 16-row unit (4 KB contiguous in gmem), XOR-swizzled dst
static __device__ __forceinline__ void load_unit(
    uint32_t dst_base, const float* __restrict__ src, int lane) {
#pragma unroll
    for (int i = 0; i < 8; i++) {
        int idx = i * 32 + lane;            // 256 16B-chunks
        int r = idx >> 4, c = idx & 15;
        cp16(dst_base + (uint32_t)(r * 256 + ((c ^ (r & 7)) << 4)),
             src + (size_t)idx * 4);
    }
}

// ---------------- kernel ----------------
__global__ void __launch_bounds__(THREADS, 1) fused_lin_lse_mish(
    const float* __restrict__ x, const float* __restrict__ W,
    float* __restrict__ out) {
    extern __shared__ char smem[];
    const uint32_t sb = smem_u32(smem);
    const int tid  = threadIdx.x;
    const int lane = tid & 31;
    const int w    = tid >> 5;
    const int g    = lane >> 2;          // 0..7
    const int t    = lane & 3;           // 0..3

    // ---- build fragment-major W (FB): entry e=(kb*4+j)*32+lane holds
    //      {W[g+2j*8][8kb+t], W[g+2j*8][8kb+4+t], W[g+(2j+1)*8][8kb+t], W[g+(2j+1)*8][8kb+4+t]}
#pragma unroll
    for (int h = 0; h < 2; h++) {
        int e  = h * THREADS + tid;       // 1024 entries
        int el = e & 31, j = (e >> 5) & 3, kb = e >> 7;
        int eg = el >> 2, et = el & 3;
        int n0 = eg + 2 * j * 8, n1 = n0 + 8;
        int k0 = 8 * kb + et;
        uint4 v;
        v.x = f2tf32(W[n0 * 64 + k0]);
        v.y = f2tf32(W[n0 * 64 + k0 + 4]);
        v.z = f2tf32(W[n1 * 64 + k0]);
        v.w = f2tf32(W[n1 * 64 + k0 + 4]);
        *reinterpret_cast<uint4*>(smem + e * 16) = v;
    }

    const size_t wrow0 = (size_t)blockIdx.x * (WARPS * ROWS_WARP) + (size_t)w * ROWS_WARP;
    const uint32_t ring = sb + SMEM_X + (uint32_t)w * (NSLOTS * UNIT_BYTES);

    // ---- prologue: units 0,1,2 into slots 0,1,2 ----
#pragma unroll
    for (int u = 0; u < NSLOTS; u++) {
        load_unit(ring + (uint32_t)u * UNIT_BYTES,
                  x + (wrow0 + (size_t)u * UNIT_ROWS) * 64, lane);
        CP_COMMIT();
    }

    __syncthreads();                      // FB visible to all warps

    const uint32_t tq = (uint32_t)(t * 4);

#pragma unroll
    for (int c = 0; c < NCHUNK; c++) {
        CP_WAIT1();                       // units 2c, 2c+1 resident (warp-private)

        const uint32_t A0 = (uint32_t)(SMEM_X + w * (NSLOTS * UNIT_BYTES)
                                       + ((2 * c) % NSLOTS) * UNIT_BYTES);
        const uint32_t A1 = (uint32_t)(SMEM_X + w * (NSLOTS * UNIT_BYTES)
                                       + ((2 * c + 1) % NSLOTS) * UNIT_BYTES);

        float acc[2][8][4];
#pragma unroll
        for (int mt = 0; mt < 2; mt++)
#pragma unroll
            for (int nb = 0; nb < 8; nb++)
#pragma unroll
                for (int q = 0; q < 4; q++) acc[mt][nb][q] = 0.0f;

#pragma unroll
        for (int kb = 0; kb < 8; kb++) {
            const uint32_t cx0 = (uint32_t)((((2 * kb) ^ g) << 4)) + tq;
            const uint32_t cx1 = (uint32_t)((((2 * kb + 1) ^ g) << 4)) + tq;
            uint32_t a0[4], a1[4];
            a0[0] = lds32(smem, A0 + (uint32_t)(g * 256) + cx0);
            a0[1] = lds32(smem, A0 + (uint32_t)((g + 8) * 256) + cx0);
            a0[2] = lds32(smem, A0 + (uint32_t)(g * 256) + cx1);
            a0[3] = lds32(smem, A0 + (uint32_t)((g + 8) * 256) + cx1);
            a1[0] = lds32(smem, A1 + (uint32_t)(g * 256) + cx0);
            a1[1] = lds32(smem, A1 + (uint32_t)((g + 8) * 256) + cx0);
            a1[2] = lds32(smem, A1 + (uint32_t)(g * 256) + cx1);
            a1[3] = lds32(smem, A1 + (uint32_t)((g + 8) * 256) + cx1);

            uint32_t b[8][2];
#pragma unroll
            for (int j = 0; j < 4; j++) {
                uint4 bv = *reinterpret_cast<const uint4*>(
                    smem + ((kb * 4 + j) * 32 + lane) * 16);
                b[2 * j][0]     = bv.x;
                b[2 * j][1]     = bv.y;
                b[2 * j + 1][0] = bv.z;
                b[2 * j + 1][1] = bv.w;
            }
#pragma unroll
            for (int nb = 0; nb < 8; nb++) {
                mma_tf32(acc[0][nb], a0, b[nb][0], b[nb][1]);
                mma_tf32(acc[1][nb], a1, b[nb][0], b[nb][1]);
            }
        }

        // ---- epilogue ----
#pragma unroll
        for (int mt = 0; mt < 2; mt++) {
            float sl = 0.0f, sh = 0.0f;
#pragma unroll
            for (int nb = 0; nb < 8; nb++) {
                sl += expv(acc[mt][nb][0]) + expv(acc[mt][nb][1]);
                sh += expv(acc[mt][nb][2]) + expv(acc[mt][nb][3]);
            }
            sl += __shfl_xor_sync(0xFFFFFFFF, sl, 1);
            sl += __shfl_xor_sync(0xFFFFFFFF, sl, 2);
            sh += __shfl_xor_sync(0xFFFFFFFF, sh, 1);
            sh += __shfl_xor_sync(0xFFFFFFFF, sh, 2);
            if (t == 0) {
                size_t row = wrow0 + (size_t)c * 32 + mt * 16 + g;
                out[row]     = mish_of_ln(sl);
                out[row + 8] = mish_of_ln(sh);
            }
        }

        // ---- refill consumed slots with units 2c+3, 2c+4 (2 commits/iter) ----
        {
            int u = 2 * c + 3;
            if (u < 2 * NCHUNK)
                load_unit(ring + (uint32_t)((u % NSLOTS)) * UNIT_BYTES,
                          x + (wrow0 + (size_t)u * UNIT_ROWS) * 64, lane);
            CP_COMMIT();
            u = 2 * c + 4;
            if (u < 2 * NCHUNK)
                load_unit(ring + (uint32_t)((u % NSLOTS)) * UNIT_BYTES,
                          x + (wrow0 + (size_t)u * UNIT_ROWS) * 64, lane);
            CP_COMMIT();
        }
    }
}

// ---------------- launch ----------------
extern "C" void kernel_launch(void* const* d_in, const int* in_sizes, int n_in,
                              void* d_out, int out_size) {
    (void)in_sizes; (void)n_in; (void)out_size;
    const float* x = (const float*)d_in[0];
    const float* W = (const float*)d_in[1];
    float* out = (float*)d_out;

    cudaFuncSetAttribute(fused_lin_lse_mish,
                         cudaFuncAttributeMaxDynamicSharedMemorySize, SMEM_TOTAL);
    fused_lin_lse_mish<<<CTAS, THREADS, SMEM_TOTAL>>>(x, W, out);
}